// round 1
// baseline (speedup 1.0000x reference)
#include <cuda_runtime.h>

#define B 8192
#define D 256
#define BM 128
#define BN 128
#define BK 32
#define NSPLIT 8
#define JCHUNK (B / NSPLIT)

// SMEM row padding to reduce transposed-store bank conflicts
#define LDA (BM + 4)

__device__ float g_xn[B * D];
__device__ float g_pos_part[NSPLIT * B];
__device__ float g_neg_part[NSPLIT * B];

// ---------------------------------------------------------------------------
// 1) Row-normalize embeddings: x_hat = x / max(||x||, 1e-12)
// ---------------------------------------------------------------------------
__global__ void normalize_kernel(const float* __restrict__ x) {
    const int row = blockIdx.x;
    const int t = threadIdx.x;  // 256 threads, one element each
    float v = x[row * D + t];

    __shared__ float red[256];
    red[t] = v * v;
    __syncthreads();
    #pragma unroll
    for (int s = 128; s > 0; s >>= 1) {
        if (t < s) red[t] += red[t + s];
        __syncthreads();
    }
    float inv = 1.0f / fmaxf(sqrtf(red[0]), 1e-12f);
    g_xn[row * D + t] = v * inv;
}

// ---------------------------------------------------------------------------
// 2) Fused Gram-tile + hard-mining kernel.
//    CTA = (i-tile of 128 rows) x (1/NSPLIT of j range).
//    256 threads, each owns an 8x8 microtile of the 128x128 dist tile.
//    Per-row running posmax / negmin kept in registers across j-tiles,
//    reduced across the 16 threads sharing a row set at the end.
// ---------------------------------------------------------------------------
__global__ __launch_bounds__(256, 2) void tile_kernel(const int* __restrict__ labels) {
    const int i0 = blockIdx.x * BM;
    const int split = blockIdx.y;
    const int tid = threadIdx.x;
    const int tx = tid & 15;   // column group (n)
    const int ty = tid >> 4;   // row group (m)

    __shared__ float sA[BK][LDA];
    __shared__ float sB[BK][LDA];

    float posmax[8], negmin[8];
    int labi[8];
    const int myrow = i0 + ty * 8;
    #pragma unroll
    for (int r = 0; r < 8; r++) {
        posmax[r] = -1e9f;
        negmin[r] = 1e9f;
        labi[r] = labels[myrow + r];
    }

    for (int jt = 0; jt < JCHUNK / BN; jt++) {
        const int j0 = split * JCHUNK + jt * BN;

        float acc[8][8];
        #pragma unroll
        for (int r = 0; r < 8; r++)
            #pragma unroll
            for (int c = 0; c < 8; c++) acc[r][c] = 0.0f;

        for (int kk = 0; kk < D; kk += BK) {
            // Load 128x32 tiles of A (rows i0..) and B (rows j0..), transposed
            // into smem as [k][m]. 1024 float4 slots per tile, 4 per thread.
            #pragma unroll
            for (int q = 0; q < 4; q++) {
                int slot = tid + q * 256;
                int row = slot >> 3;       // 0..127
                int f4 = slot & 7;         // 0..7 -> k offset f4*4
                float4 a = *(const float4*)&g_xn[(i0 + row) * D + kk + f4 * 4];
                sA[f4 * 4 + 0][row] = a.x;
                sA[f4 * 4 + 1][row] = a.y;
                sA[f4 * 4 + 2][row] = a.z;
                sA[f4 * 4 + 3][row] = a.w;
                float4 b = *(const float4*)&g_xn[(j0 + row) * D + kk + f4 * 4];
                sB[f4 * 4 + 0][row] = b.x;
                sB[f4 * 4 + 1][row] = b.y;
                sB[f4 * 4 + 2][row] = b.z;
                sB[f4 * 4 + 3][row] = b.w;
            }
            __syncthreads();

            #pragma unroll
            for (int k = 0; k < BK; k++) {
                float a[8], b[8];
                #pragma unroll
                for (int r = 0; r < 8; r++) a[r] = sA[k][ty * 8 + r];
                #pragma unroll
                for (int c = 0; c < 8; c++) b[c] = sB[k][tx * 8 + c];
                #pragma unroll
                for (int r = 0; r < 8; r++)
                    #pragma unroll
                    for (int c = 0; c < 8; c++) acc[r][c] = fmaf(a[r], b[c], acc[r][c]);
            }
            __syncthreads();
        }

        // Fused epilogue: dist = max(0, 1 - dot); masked max/min per anchor row
        int labj[8];
        #pragma unroll
        for (int c = 0; c < 8; c++) labj[c] = labels[j0 + tx * 8 + c];

        #pragma unroll
        for (int r = 0; r < 8; r++) {
            const int m = myrow + r;
            const int li = labi[r];
            #pragma unroll
            for (int c = 0; c < 8; c++) {
                const int n = j0 + tx * 8 + c;
                float dist = fmaxf(1.0f - acc[r][c], 0.0f);
                bool same = (li == labj[c]);
                if (same) {
                    if (m != n) posmax[r] = fmaxf(posmax[r], dist);
                } else {
                    negmin[r] = fminf(negmin[r], dist);
                }
            }
        }
    }

    // Reduce across the 16 tx-threads that share this row set.
    // lane = tid % 32 = (ty&1)*16 + tx, so xor offsets 8,4,2,1 stay within
    // the 16-lane group holding identical rows.
    #pragma unroll
    for (int r = 0; r < 8; r++) {
        #pragma unroll
        for (int off = 8; off > 0; off >>= 1) {
            posmax[r] = fmaxf(posmax[r], __shfl_xor_sync(0xffffffffu, posmax[r], off));
            negmin[r] = fminf(negmin[r], __shfl_xor_sync(0xffffffffu, negmin[r], off));
        }
    }
    if (tx == 0) {
        #pragma unroll
        for (int r = 0; r < 8; r++) {
            g_pos_part[split * B + myrow + r] = posmax[r];
            g_neg_part[split * B + myrow + r] = negmin[r];
        }
    }
}

// ---------------------------------------------------------------------------
// 3) Combine split partials -> per-anchor loss -> mean over valid anchors
// ---------------------------------------------------------------------------
__global__ void combine_kernel(float* __restrict__ out) {
    __shared__ float ssum[256];
    __shared__ int scnt[256];
    const int t = threadIdx.x;

    float sum = 0.0f;
    int cnt = 0;
    for (int row = t; row < B; row += 256) {
        float p = -1e9f, n = 1e9f;
        #pragma unroll
        for (int s = 0; s < NSPLIT; s++) {
            p = fmaxf(p, g_pos_part[s * B + row]);
            n = fminf(n, g_neg_part[s * B + row]);
        }
        bool valid = (p > -1e8f) && (n < 1e8f);
        float per = fmaxf(p - n + 1.0f, 0.0f);  // MARGIN = 1.0
        if (valid) {
            sum += per;
            cnt++;
        }
    }
    ssum[t] = sum;
    scnt[t] = cnt;
    __syncthreads();
    #pragma unroll
    for (int s = 128; s > 0; s >>= 1) {
        if (t < s) {
            ssum[t] += ssum[t + s];
            scnt[t] += scnt[t + s];
        }
        __syncthreads();
    }
    if (t == 0) {
        float c = (float)scnt[0];
        out[0] = (c > 0.0f) ? (ssum[0] / fmaxf(c, 1.0f)) : 0.0f;
    }
}

// ---------------------------------------------------------------------------
extern "C" void kernel_launch(void* const* d_in, const int* in_sizes, int n_in,
                              void* d_out, int out_size) {
    const float* emb = (const float*)d_in[0];
    const int* labels = (const int*)d_in[1];
    float* out = (float*)d_out;

    normalize_kernel<<<B, 256>>>(emb);
    dim3 grid(B / BM, NSPLIT);
    tile_kernel<<<grid, 256>>>(labels);
    combine_kernel<<<1, 256>>>(out);
}

// round 3
// speedup vs baseline: 7.6523x; 7.6523x over previous
#include <cuda_runtime.h>
#include <cuda_fp16.h>
#include <cstdint>

#define B 8192
#define D 256
#define NSPLIT 4
#define JCHUNK (B / NSPLIT)      // 2048
#define NJT (JCHUNK / 128)       // 16 j-tiles per CTA

__device__ __half g_xh[B * D];
__device__ float g_pos_part[NSPLIT * B];
__device__ float g_neg_part[NSPLIT * B];

// ---- dynamic smem layout (bytes)
#define SM_A     0                 // 8 slabs x [128][32] halves = 65536
#define SM_B0    65536             // 8192
#define SM_B1    73728             // 8192
#define SM_JLAB  81920             // 512
#define SM_SPOS  82432             // 1024
#define SM_SNEG  83456             // 1024
#define SMEM_TOTAL 84480

__device__ __forceinline__ uint32_t smem_u32(const void* p) {
    uint32_t a;
    asm("{ .reg .u64 t; cvta.to.shared.u64 t, %1; cvt.u32.u64 %0, t; }" : "=r"(a) : "l"(p));
    return a;
}

// physical byte offset of 16B chunk c in row r (conflict-free for ldmatrix + cp.async)
__device__ __forceinline__ uint32_t swz(int r, int c) {
    return (uint32_t)(r * 64 + ((c ^ ((r >> 1) & 3)) << 4));
}

#define CP_ASYNC16(dst, src) \
    asm volatile("cp.async.cg.shared.global [%0], [%1], 16;" :: "r"(dst), "l"(src) : "memory")
#define CP_COMMIT() asm volatile("cp.async.commit_group;" ::: "memory")

__device__ __forceinline__ void ldsm_x4(uint32_t* f, uint32_t addr) {
    asm volatile("ldmatrix.sync.aligned.m8n8.x4.shared.b16 {%0,%1,%2,%3}, [%4];"
                 : "=r"(f[0]), "=r"(f[1]), "=r"(f[2]), "=r"(f[3]) : "r"(addr));
}

__device__ __forceinline__ void mma16816(float* d, const uint32_t* a, uint32_t b0, uint32_t b1) {
    asm volatile(
        "mma.sync.aligned.m16n8k16.row.col.f32.f16.f16.f32 "
        "{%0,%1,%2,%3}, {%4,%5,%6,%7}, {%8,%9}, {%0,%1,%2,%3};"
        : "+f"(d[0]), "+f"(d[1]), "+f"(d[2]), "+f"(d[3])
        : "r"(a[0]), "r"(a[1]), "r"(a[2]), "r"(a[3]), "r"(b0), "r"(b1));
}

// ====================== 1) normalize -> fp16 ======================
__global__ void normalize_kernel(const float* __restrict__ x) {
    const int row = (blockIdx.x * blockDim.x + threadIdx.x) >> 5;
    const int lane = threadIdx.x & 31;
    const float4* src = (const float4*)&x[(size_t)row * D];
    float4 a = src[lane];
    float4 b = src[lane + 32];
    float s = a.x*a.x + a.y*a.y + a.z*a.z + a.w*a.w
            + b.x*b.x + b.y*b.y + b.z*b.z + b.w*b.w;
    #pragma unroll
    for (int o = 16; o > 0; o >>= 1) s += __shfl_xor_sync(0xffffffffu, s, o);
    const float inv = 1.0f / fmaxf(sqrtf(s), 1e-12f);
    __half2* dst = (__half2*)&g_xh[(size_t)row * D];
    dst[lane*2 + 0]  = __floats2half2_rn(a.x * inv, a.y * inv);
    dst[lane*2 + 1]  = __floats2half2_rn(a.z * inv, a.w * inv);
    dst[lane*2 + 64] = __floats2half2_rn(b.x * inv, b.y * inv);
    dst[lane*2 + 65] = __floats2half2_rn(b.z * inv, b.w * inv);
}

// ====================== 2) fused mma.sync Gram + hard mining ======================
__global__ __launch_bounds__(256, 2) void tile_kernel(const int* __restrict__ labels) {
    extern __shared__ char smem[];
    const uint32_t sb = smem_u32(smem);
    const int tid = threadIdx.x;
    const int lane = tid & 31, wid = tid >> 5;
    const int wm = wid & 3, wn = wid >> 2;     // warp grid 4(m) x 2(n)
    const int i0 = blockIdx.x * 128;
    const int jbase = blockIdx.y * JCHUNK;

    // ---- prologue: A tile (128 rows x 256 halves) into 8 k-slabs of [128][32]
    #pragma unroll
    for (int q = 0; q < 16; q++) {
        const int g = q * 256 + tid;
        const int slab = g >> 9, w = g & 511, r = w >> 2, c = w & 3;
        const uint32_t dst = sb + SM_A + slab * 8192 + swz(r, c);
        const __half* src = &g_xh[(size_t)(i0 + r) * D + slab * 32 + c * 8];
        CP_ASYNC16(dst, src);
    }
    CP_COMMIT();

    // per-lane ldmatrix offsets
    const int lr = (lane & 7) + ((lane >> 3) & 1) * 8;  // row within 16
    const int lc = lane >> 4;                           // k-half select
    uint32_t a_off[2][2], b_off[4][2];
    #pragma unroll
    for (int mi = 0; mi < 2; mi++) {
        const int rA = wm * 32 + mi * 16 + lr;
        #pragma unroll
        for (int ks = 0; ks < 2; ks++) a_off[mi][ks] = swz(rA, 2 * ks + lc);
    }
    #pragma unroll
    for (int pr = 0; pr < 4; pr++) {
        const int rB = wn * 64 + pr * 16 + lr;
        #pragma unroll
        for (int ks = 0; ks < 2; ks++) b_off[pr][ks] = swz(rB, 2 * ks + lc);
    }

    // labels of the 4 rows this lane owns
    int labm[2][2];
    #pragma unroll
    for (int mi = 0; mi < 2; mi++)
        #pragma unroll
        for (int hb = 0; hb < 2; hb++)
            labm[mi][hb] = __ldg(&labels[i0 + wm * 32 + mi * 16 + hb * 8 + (lane >> 2)]);

    float posmax[2][2], negmin[2][2];
    #pragma unroll
    for (int mi = 0; mi < 2; mi++)
        #pragma unroll
        for (int hb = 0; hb < 2; hb++) { posmax[mi][hb] = -1e9f; negmin[mi][hb] = 1e9f; }

    for (int t = 0; t < NJT; t++) {
        const int j0 = jbase + t * 128;
        if (tid < 128) ((int*)(smem + SM_JLAB))[tid] = labels[j0 + tid];

        float d[2][8][4];
        #pragma unroll
        for (int mi = 0; mi < 2; mi++)
            #pragma unroll
            for (int ni = 0; ni < 8; ni++)
                #pragma unroll
                for (int e = 0; e < 4; e++) d[mi][ni][e] = 0.0f;

        // B slab kk=0 -> buf0
        {
            #pragma unroll
            for (int q = 0; q < 2; q++) {
                const int w = q * 256 + tid, r = w >> 2, c = w & 3;
                CP_ASYNC16(sb + SM_B0 + swz(r, c),
                           &g_xh[(size_t)(j0 + r) * D + c * 8]);
            }
            CP_COMMIT();
        }

        #pragma unroll
        for (int kk = 0; kk < 8; kk++) {
            if (kk < 7) {
                const uint32_t buf = sb + ((kk & 1) ? SM_B0 : SM_B1);  // next buffer
                #pragma unroll
                for (int q = 0; q < 2; q++) {
                    const int w = q * 256 + tid, r = w >> 2, c = w & 3;
                    CP_ASYNC16(buf + swz(r, c),
                               &g_xh[(size_t)(j0 + r) * D + (kk + 1) * 32 + c * 8]);
                }
                CP_COMMIT();
                asm volatile("cp.async.wait_group 1;" ::: "memory");
            } else {
                asm volatile("cp.async.wait_group 0;" ::: "memory");
            }
            __syncthreads();

            const uint32_t sa = sb + SM_A + kk * 8192;
            const uint32_t sbuf = sb + ((kk & 1) ? SM_B1 : SM_B0);
            #pragma unroll
            for (int ks = 0; ks < 2; ks++) {
                uint32_t a[2][4];
                ldsm_x4(a[0], sa + a_off[0][ks]);
                ldsm_x4(a[1], sa + a_off[1][ks]);
                uint32_t bf[4][4];
                #pragma unroll
                for (int pr = 0; pr < 4; pr++) ldsm_x4(bf[pr], sbuf + b_off[pr][ks]);
                #pragma unroll
                for (int mi = 0; mi < 2; mi++)
                    #pragma unroll
                    for (int pr = 0; pr < 4; pr++)
                        #pragma unroll
                        for (int sub = 0; sub < 2; sub++)
                            mma16816(d[mi][pr * 2 + sub], a[mi], bf[pr][sub], bf[pr][sub + 2]);
            }
            __syncthreads();
        }

        // fused epilogue
        const int* jl = (const int*)(smem + SM_JLAB);
        #pragma unroll
        for (int ni = 0; ni < 8; ni++) {
            const int colb = wn * 64 + ni * 8 + (lane & 3) * 2;
            const int l0 = jl[colb], l1 = jl[colb + 1];
            const int n0 = j0 + colb;
            #pragma unroll
            for (int mi = 0; mi < 2; mi++) {
                const int mrow = i0 + wm * 32 + mi * 16 + (lane >> 2);
                #pragma unroll
                for (int e = 0; e < 4; e++) {
                    const int hb = e >> 1;
                    const int m = mrow + hb * 8;
                    const int n = n0 + (e & 1);
                    const int ln = (e & 1) ? l1 : l0;
                    const float dist = fmaxf(1.0f - d[mi][ni][e], 0.0f);
                    if (ln == labm[mi][hb]) {
                        if (m != n) posmax[mi][hb] = fmaxf(posmax[mi][hb], dist);
                    } else {
                        negmin[mi][hb] = fminf(negmin[mi][hb], dist);
                    }
                }
            }
        }
    }

    // reduce across the 4 lanes sharing each row (quad), then across warp_n
    #pragma unroll
    for (int mi = 0; mi < 2; mi++)
        #pragma unroll
        for (int hb = 0; hb < 2; hb++) {
            #pragma unroll
            for (int off = 1; off <= 2; off <<= 1) {
                posmax[mi][hb] = fmaxf(posmax[mi][hb], __shfl_xor_sync(0xffffffffu, posmax[mi][hb], off));
                negmin[mi][hb] = fminf(negmin[mi][hb], __shfl_xor_sync(0xffffffffu, negmin[mi][hb], off));
            }
        }
    float* spos = (float*)(smem + SM_SPOS);
    float* sneg = (float*)(smem + SM_SNEG);
    if ((lane & 3) == 0) {
        const int gid = lane >> 2;
        #pragma unroll
        for (int mi = 0; mi < 2; mi++)
            #pragma unroll
            for (int hb = 0; hb < 2; hb++) {
                const int row = wm * 32 + mi * 16 + hb * 8 + gid;
                spos[wn * 128 + row] = posmax[mi][hb];
                sneg[wn * 128 + row] = negmin[mi][hb];
            }
    }
    __syncthreads();
    if (tid < 128) {
        g_pos_part[blockIdx.y * B + i0 + tid] = fmaxf(spos[tid], spos[128 + tid]);
        g_neg_part[blockIdx.y * B + i0 + tid] = fminf(sneg[tid], sneg[128 + tid]);
    }
}

// ====================== 3) combine ======================
__global__ void combine_kernel(float* __restrict__ out) {
    __shared__ float ssum[256];
    __shared__ int scnt[256];
    const int t = threadIdx.x;
    float sum = 0.0f;
    int cnt = 0;
    for (int row = t; row < B; row += 256) {
        float p = -1e9f, n = 1e9f;
        #pragma unroll
        for (int s = 0; s < NSPLIT; s++) {
            p = fmaxf(p, g_pos_part[s * B + row]);
            n = fminf(n, g_neg_part[s * B + row]);
        }
        const bool valid = (p > -1e8f) && (n < 1e8f);
        const float per = fmaxf(p - n + 1.0f, 0.0f);  // MARGIN = 1.0
        if (valid) { sum += per; cnt++; }
    }
    ssum[t] = sum; scnt[t] = cnt;
    __syncthreads();
    #pragma unroll
    for (int s = 128; s > 0; s >>= 1) {
        if (t < s) { ssum[t] += ssum[t + s]; scnt[t] += scnt[t + s]; }
        __syncthreads();
    }
    if (t == 0) {
        const float c = (float)scnt[0];
        out[0] = (c > 0.0f) ? (ssum[0] / fmaxf(c, 1.0f)) : 0.0f;
    }
}

// ======================================================================
extern "C" void kernel_launch(void* const* d_in, const int* in_sizes, int n_in,
                              void* d_out, int out_size) {
    const float* emb = (const float*)d_in[0];
    const int* labels = (const int*)d_in[1];
    float* out = (float*)d_out;

    cudaFuncSetAttribute(tile_kernel, cudaFuncAttributeMaxDynamicSharedMemorySize, SMEM_TOTAL);

    normalize_kernel<<<B / 8, 256>>>(emb);
    tile_kernel<<<dim3(B / 128, NSPLIT), 256, SMEM_TOTAL>>>(labels);
    combine_kernel<<<1, 256>>>(out);
}

// round 4
// speedup vs baseline: 13.2965x; 1.7376x over previous
#include <cuda_runtime.h>
#include <cuda_fp16.h>
#include <cstdint>

#define B 8192
#define D 256
#define NT 64                     // 128-row tiles per dimension
#define NSLOT 64

__device__ __half g_xh[B * D];
__device__ float g_pos_part[NSLOT * B];   // 2M floats
__device__ float g_neg_part[NSLOT * B];
__device__ float g_sum;
__device__ int g_cnt;

// ---- dynamic smem layout (bytes)
#define SM_A     0                 // 8 slabs x [128][32] halves = 65536
#define SM_B0    65536             // 8192
#define SM_B1    73728             // 8192
#define SM_JLAB  81920             // 512
#define SM_RPOS  82432             // [2][128] f32 = 1024
#define SM_RNEG  83456             // 1024
#define SM_CPOS  84480             // [4][128] f32 = 2048
#define SM_CNEG  86528             // 2048
#define SMEM_TOTAL 88576

__device__ __forceinline__ uint32_t smem_u32(const void* p) {
    uint32_t a;
    asm("{ .reg .u64 t; cvta.to.shared.u64 t, %1; cvt.u32.u64 %0, t; }" : "=r"(a) : "l"(p));
    return a;
}

// physical byte offset of 16B chunk c in row r (conflict-free ldmatrix + cp.async)
__device__ __forceinline__ uint32_t swz(int r, int c) {
    return (uint32_t)(r * 64 + ((c ^ ((r >> 1) & 3)) << 4));
}

#define CP_ASYNC16(dst, src) \
    asm volatile("cp.async.cg.shared.global [%0], [%1], 16;" :: "r"(dst), "l"(src) : "memory")
#define CP_COMMIT() asm volatile("cp.async.commit_group;" ::: "memory")

__device__ __forceinline__ void ldsm_x4(uint32_t* f, uint32_t addr) {
    asm volatile("ldmatrix.sync.aligned.m8n8.x4.shared.b16 {%0,%1,%2,%3}, [%4];"
                 : "=r"(f[0]), "=r"(f[1]), "=r"(f[2]), "=r"(f[3]) : "r"(addr));
}

__device__ __forceinline__ void mma16816(float* d, const uint32_t* a, uint32_t b0, uint32_t b1) {
    asm volatile(
        "mma.sync.aligned.m16n8k16.row.col.f32.f16.f16.f32 "
        "{%0,%1,%2,%3}, {%4,%5,%6,%7}, {%8,%9}, {%0,%1,%2,%3};"
        : "+f"(d[0]), "+f"(d[1]), "+f"(d[2]), "+f"(d[3])
        : "r"(a[0]), "r"(a[1]), "r"(a[2]), "r"(a[3]), "r"(b0), "r"(b1));
}

// ====================== 1) normalize -> fp16 ======================
__global__ void normalize_kernel(const float* __restrict__ x) {
    const int row = (blockIdx.x * blockDim.x + threadIdx.x) >> 5;
    const int lane = threadIdx.x & 31;
    const float4* src = (const float4*)&x[(size_t)row * D];
    float4 a = src[lane];
    float4 b = src[lane + 32];
    float s = a.x*a.x + a.y*a.y + a.z*a.z + a.w*a.w
            + b.x*b.x + b.y*b.y + b.z*b.z + b.w*b.w;
    #pragma unroll
    for (int o = 16; o > 0; o >>= 1) s += __shfl_xor_sync(0xffffffffu, s, o);
    const float inv = 1.0f / fmaxf(sqrtf(s), 1e-12f);
    __half2* dst = (__half2*)&g_xh[(size_t)row * D];
    dst[lane*2 + 0]  = __floats2half2_rn(a.x * inv, a.y * inv);
    dst[lane*2 + 1]  = __floats2half2_rn(a.z * inv, a.w * inv);
    dst[lane*2 + 64] = __floats2half2_rn(b.x * inv, b.y * inv);
    dst[lane*2 + 65] = __floats2half2_rn(b.z * inv, b.w * inv);
}

__global__ void init_kernel() { g_sum = 0.0f; g_cnt = 0; }

// ====================== 2) upper-triangular fused tile kernel ======================
// CTA (ti = blockIdx.y, tj = blockIdx.x), only tj >= ti does work.
// Mines rows of block ti over the tile columns (slot tj) AND, via symmetry,
// rows of block tj over the tile rows (slot ti; skipped on diagonal).
__global__ __launch_bounds__(256, 2) void tile_kernel(const int* __restrict__ labels) {
    const int ti = blockIdx.y, tj = blockIdx.x;
    if (tj < ti) return;

    extern __shared__ char smem[];
    const uint32_t sb = smem_u32(smem);
    const int tid = threadIdx.x;
    const int lane = tid & 31, wid = tid >> 5;
    const int wm = wid & 3, wn = wid >> 2;     // warp grid 4(m) x 2(n)
    const int i0 = ti * 128;
    const int j0 = tj * 128;

    if (tid < 128) ((int*)(smem + SM_JLAB))[tid] = labels[j0 + tid];

    // ---- prologue: A tile (128 rows x 256 halves) into 8 k-slabs of [128][32]
    #pragma unroll
    for (int q = 0; q < 16; q++) {
        const int g = q * 256 + tid;
        const int slab = g >> 9, w = g & 511, r = w >> 2, c = w & 3;
        CP_ASYNC16(sb + SM_A + slab * 8192 + swz(r, c),
                   &g_xh[(size_t)(i0 + r) * D + slab * 32 + c * 8]);
    }
    CP_COMMIT();

    // B slab kk=0 -> buf0
    #pragma unroll
    for (int q = 0; q < 2; q++) {
        const int w = q * 256 + tid, r = w >> 2, c = w & 3;
        CP_ASYNC16(sb + SM_B0 + swz(r, c), &g_xh[(size_t)(j0 + r) * D + c * 8]);
    }
    CP_COMMIT();

    // per-lane ldmatrix offsets
    const int lr = (lane & 7) + ((lane >> 3) & 1) * 8;
    const int lc = lane >> 4;
    uint32_t a_off[2][2], b_off[4][2];
    #pragma unroll
    for (int mi = 0; mi < 2; mi++) {
        const int rA = wm * 32 + mi * 16 + lr;
        #pragma unroll
        for (int ks = 0; ks < 2; ks++) a_off[mi][ks] = swz(rA, 2 * ks + lc);
    }
    #pragma unroll
    for (int pr = 0; pr < 4; pr++) {
        const int rB = wn * 64 + pr * 16 + lr;
        #pragma unroll
        for (int ks = 0; ks < 2; ks++) b_off[pr][ks] = swz(rB, 2 * ks + lc);
    }

    int labm[2][2];
    #pragma unroll
    for (int mi = 0; mi < 2; mi++)
        #pragma unroll
        for (int hb = 0; hb < 2; hb++)
            labm[mi][hb] = __ldg(&labels[i0 + wm * 32 + mi * 16 + hb * 8 + (lane >> 2)]);

    float d[2][8][4];
    #pragma unroll
    for (int mi = 0; mi < 2; mi++)
        #pragma unroll
        for (int ni = 0; ni < 8; ni++)
            #pragma unroll
            for (int e = 0; e < 4; e++) d[mi][ni][e] = 0.0f;

    #pragma unroll
    for (int kk = 0; kk < 8; kk++) {
        if (kk < 7) {
            const uint32_t buf = sb + ((kk & 1) ? SM_B0 : SM_B1);
            #pragma unroll
            for (int q = 0; q < 2; q++) {
                const int w = q * 256 + tid, r = w >> 2, c = w & 3;
                CP_ASYNC16(buf + swz(r, c),
                           &g_xh[(size_t)(j0 + r) * D + (kk + 1) * 32 + c * 8]);
            }
            CP_COMMIT();
            asm volatile("cp.async.wait_group 1;" ::: "memory");
        } else {
            asm volatile("cp.async.wait_group 0;" ::: "memory");
        }
        __syncthreads();

        const uint32_t sa = sb + SM_A + kk * 8192;
        const uint32_t sbuf = sb + ((kk & 1) ? SM_B1 : SM_B0);
        #pragma unroll
        for (int ks = 0; ks < 2; ks++) {
            uint32_t a[2][4];
            ldsm_x4(a[0], sa + a_off[0][ks]);
            ldsm_x4(a[1], sa + a_off[1][ks]);
            uint32_t bf[4][4];
            #pragma unroll
            for (int pr = 0; pr < 4; pr++) ldsm_x4(bf[pr], sbuf + b_off[pr][ks]);
            #pragma unroll
            for (int mi = 0; mi < 2; mi++)
                #pragma unroll
                for (int pr = 0; pr < 4; pr++)
                    #pragma unroll
                    for (int sub = 0; sub < 2; sub++)
                        mma16816(d[mi][pr * 2 + sub], a[mi], bf[pr][sub], bf[pr][sub + 2]);
        }
        __syncthreads();
    }

    // ================= fused epilogue: row + column mining =================
    const int* jl = (const int*)(smem + SM_JLAB);
    float* scpos = (float*)(smem + SM_CPOS);
    float* scneg = (float*)(smem + SM_CNEG);

    float posmax[2][2], negmin[2][2];
    #pragma unroll
    for (int mi = 0; mi < 2; mi++)
        #pragma unroll
        for (int hb = 0; hb < 2; hb++) { posmax[mi][hb] = -1e9f; negmin[mi][hb] = 1e9f; }

    #pragma unroll
    for (int ni = 0; ni < 8; ni++) {
        const int colb = wn * 64 + ni * 8 + (lane & 3) * 2;
        const int l0 = jl[colb], l1 = jl[colb + 1];
        const int n0 = j0 + colb;
        float cp[2] = {-1e9f, -1e9f}, cn[2] = {1e9f, 1e9f};
        #pragma unroll
        for (int mi = 0; mi < 2; mi++) {
            #pragma unroll
            for (int e = 0; e < 4; e++) {
                const int hb = e >> 1, c01 = e & 1;
                const int m = i0 + wm * 32 + mi * 16 + hb * 8 + (lane >> 2);
                const int n = n0 + c01;
                const int ln = c01 ? l1 : l0;
                const float dist = fmaxf(1.0f - d[mi][ni][e], 0.0f);
                if (ln == labm[mi][hb]) {
                    if (m != n) {
                        posmax[mi][hb] = fmaxf(posmax[mi][hb], dist);
                        cp[c01] = fmaxf(cp[c01], dist);
                    }
                } else {
                    negmin[mi][hb] = fminf(negmin[mi][hb], dist);
                    cn[c01] = fminf(cn[c01], dist);
                }
            }
        }
        // reduce column partials across the 8 lanes (lane>>2) sharing these columns
        #pragma unroll
        for (int off = 4; off <= 16; off <<= 1) {
            cp[0] = fmaxf(cp[0], __shfl_xor_sync(0xffffffffu, cp[0], off));
            cp[1] = fmaxf(cp[1], __shfl_xor_sync(0xffffffffu, cp[1], off));
            cn[0] = fminf(cn[0], __shfl_xor_sync(0xffffffffu, cn[0], off));
            cn[1] = fminf(cn[1], __shfl_xor_sync(0xffffffffu, cn[1], off));
        }
        if (lane < 4) {
            const int cidx = wn * 64 + ni * 8 + lane * 2;
            scpos[wm * 128 + cidx]     = cp[0];
            scpos[wm * 128 + cidx + 1] = cp[1];
            scneg[wm * 128 + cidx]     = cn[0];
            scneg[wm * 128 + cidx + 1] = cn[1];
        }
    }

    // reduce row partials across the 4 lanes sharing each row
    #pragma unroll
    for (int mi = 0; mi < 2; mi++)
        #pragma unroll
        for (int hb = 0; hb < 2; hb++) {
            #pragma unroll
            for (int off = 1; off <= 2; off <<= 1) {
                posmax[mi][hb] = fmaxf(posmax[mi][hb], __shfl_xor_sync(0xffffffffu, posmax[mi][hb], off));
                negmin[mi][hb] = fminf(negmin[mi][hb], __shfl_xor_sync(0xffffffffu, negmin[mi][hb], off));
            }
        }
    float* srpos = (float*)(smem + SM_RPOS);
    float* srneg = (float*)(smem + SM_RNEG);
    if ((lane & 3) == 0) {
        const int gid = lane >> 2;
        #pragma unroll
        for (int mi = 0; mi < 2; mi++)
            #pragma unroll
            for (int hb = 0; hb < 2; hb++) {
                const int row = wm * 32 + mi * 16 + hb * 8 + gid;
                srpos[wn * 128 + row] = posmax[mi][hb];
                srneg[wn * 128 + row] = negmin[mi][hb];
            }
    }
    __syncthreads();
    if (tid < 128) {
        // row anchors (block ti) -> slot tj
        g_pos_part[tj * B + i0 + tid] = fmaxf(srpos[tid], srpos[128 + tid]);
        g_neg_part[tj * B + i0 + tid] = fminf(srneg[tid], srneg[128 + tid]);
        // column anchors (block tj) -> slot ti (skip on diagonal; row side covers it)
        if (ti != tj) {
            float cp = fmaxf(fmaxf(scpos[tid], scpos[128 + tid]),
                             fmaxf(scpos[256 + tid], scpos[384 + tid]));
            float cn = fminf(fminf(scneg[tid], scneg[128 + tid]),
                             fminf(scneg[256 + tid], scneg[384 + tid]));
            g_pos_part[ti * B + j0 + tid] = cp;
            g_neg_part[ti * B + j0 + tid] = cn;
        }
    }
}

// ====================== 3) combine + finalize ======================
__global__ void combine_kernel() {
    const int row = blockIdx.x * 256 + threadIdx.x;
    float p = -1e9f, n = 1e9f;
    #pragma unroll 8
    for (int s = 0; s < NSLOT; s++) {
        p = fmaxf(p, g_pos_part[s * B + row]);
        n = fminf(n, g_neg_part[s * B + row]);
    }
    const bool valid = (p > -1e8f) && (n < 1e8f);
    const float per = fmaxf(p - n + 1.0f, 0.0f);  // MARGIN = 1.0

    __shared__ float ss[256];
    __shared__ int sc[256];
    const int t = threadIdx.x;
    ss[t] = valid ? per : 0.0f;
    sc[t] = valid ? 1 : 0;
    __syncthreads();
    #pragma unroll
    for (int s = 128; s > 0; s >>= 1) {
        if (t < s) { ss[t] += ss[t + s]; sc[t] += sc[t + s]; }
        __syncthreads();
    }
    if (t == 0) {
        atomicAdd(&g_sum, ss[0]);
        atomicAdd(&g_cnt, sc[0]);
    }
}

__global__ void finalize_kernel(float* __restrict__ out) {
    const float c = (float)g_cnt;
    out[0] = (c > 0.0f) ? (g_sum / fmaxf(c, 1.0f)) : 0.0f;
}

// ======================================================================
extern "C" void kernel_launch(void* const* d_in, const int* in_sizes, int n_in,
                              void* d_out, int out_size) {
    const float* emb = (const float*)d_in[0];
    const int* labels = (const int*)d_in[1];
    float* out = (float*)d_out;

    cudaFuncSetAttribute(tile_kernel, cudaFuncAttributeMaxDynamicSharedMemorySize, SMEM_TOTAL);

    normalize_kernel<<<B / 8, 256>>>(emb);
    init_kernel<<<1, 1>>>();
    tile_kernel<<<dim3(NT, NT), 256, SMEM_TOTAL>>>(labels);
    combine_kernel<<<B / 256, 256>>>();
    finalize_kernel<<<1, 1>>>(out);
}

// round 5
// speedup vs baseline: 14.1897x; 1.0672x over previous
#include <cuda_runtime.h>
#include <cuda_fp16.h>
#include <cstdint>

#define B 8192
#define D 256
#define NT 64                     // 128-row tiles per dimension
#define NSLOT 64
#define NCTA (NT * (NT + 1) / 2)  // 2080 upper-triangular tiles

__device__ __half g_xh[B * D];
__device__ float g_pos_part[NSLOT * B];
__device__ float g_neg_part[NSLOT * B];
__device__ float g_sum;
__device__ int g_cnt;
__device__ unsigned int g_done;

// ---- dynamic smem layout (bytes)
#define SM_A     0                 // 8 slabs x [128][32] halves = 65536
#define SM_B0    65536             // 8192
#define SM_B1    73728             // 8192
#define SM_JLAB  81920             // 512
#define SM_RPOS  82432             // [2][128] f32 = 1024
#define SM_RNEG  83456             // 1024
#define SM_CPOS  84480             // [4][128] f32 = 2048
#define SM_CNEG  86528             // 2048
#define SMEM_TOTAL 88576

__device__ __forceinline__ uint32_t smem_u32(const void* p) {
    uint32_t a;
    asm("{ .reg .u64 t; cvta.to.shared.u64 t, %1; cvt.u32.u64 %0, t; }" : "=r"(a) : "l"(p));
    return a;
}

// physical byte offset of 16B chunk c in row r (conflict-free ldmatrix + cp.async)
__device__ __forceinline__ uint32_t swz(int r, int c) {
    return (uint32_t)(r * 64 + ((c ^ ((r >> 1) & 3)) << 4));
}

#define CP_ASYNC16(dst, src) \
    asm volatile("cp.async.cg.shared.global [%0], [%1], 16;" :: "r"(dst), "l"(src) : "memory")
#define CP_COMMIT() asm volatile("cp.async.commit_group;" ::: "memory")

__device__ __forceinline__ void ldsm_x4(uint32_t* f, uint32_t addr) {
    asm volatile("ldmatrix.sync.aligned.m8n8.x4.shared.b16 {%0,%1,%2,%3}, [%4];"
                 : "=r"(f[0]), "=r"(f[1]), "=r"(f[2]), "=r"(f[3]) : "r"(addr));
}

__device__ __forceinline__ void mma16816(float* d, const uint32_t* a, uint32_t b0, uint32_t b1) {
    asm volatile(
        "mma.sync.aligned.m16n8k16.row.col.f32.f16.f16.f32 "
        "{%0,%1,%2,%3}, {%4,%5,%6,%7}, {%8,%9}, {%0,%1,%2,%3};"
        : "+f"(d[0]), "+f"(d[1]), "+f"(d[2]), "+f"(d[3])
        : "r"(a[0]), "r"(a[1]), "r"(a[2]), "r"(a[3]), "r"(b0), "r"(b1));
}

// ====================== 1) normalize -> fp16 (2 rows per warp) + init ======================
__global__ void normalize_kernel(const float* __restrict__ x) {
    if (blockIdx.x == 0 && threadIdx.x == 0) {
        g_sum = 0.0f; g_cnt = 0; g_done = 0u;
    }
    const int warp = (blockIdx.x * blockDim.x + threadIdx.x) >> 5;
    const int lane = threadIdx.x & 31;
    const int row0 = warp * 2;

    const float4* s0 = (const float4*)&x[(size_t)row0 * D];
    const float4* s1 = (const float4*)&x[(size_t)(row0 + 1) * D];
    float4 a = s0[lane], b = s0[lane + 32];
    float4 c = s1[lane], e = s1[lane + 32];

    float sA = a.x*a.x + a.y*a.y + a.z*a.z + a.w*a.w
             + b.x*b.x + b.y*b.y + b.z*b.z + b.w*b.w;
    float sB = c.x*c.x + c.y*c.y + c.z*c.z + c.w*c.w
             + e.x*e.x + e.y*e.y + e.z*e.z + e.w*e.w;
    #pragma unroll
    for (int o = 16; o > 0; o >>= 1) {
        sA += __shfl_xor_sync(0xffffffffu, sA, o);
        sB += __shfl_xor_sync(0xffffffffu, sB, o);
    }
    const float invA = 1.0f / fmaxf(sqrtf(sA), 1e-12f);
    const float invB = 1.0f / fmaxf(sqrtf(sB), 1e-12f);

    __half2* d0 = (__half2*)&g_xh[(size_t)row0 * D];
    __half2* d1 = (__half2*)&g_xh[(size_t)(row0 + 1) * D];
    d0[lane*2 + 0]  = __floats2half2_rn(a.x * invA, a.y * invA);
    d0[lane*2 + 1]  = __floats2half2_rn(a.z * invA, a.w * invA);
    d0[lane*2 + 64] = __floats2half2_rn(b.x * invA, b.y * invA);
    d0[lane*2 + 65] = __floats2half2_rn(b.z * invA, b.w * invA);
    d1[lane*2 + 0]  = __floats2half2_rn(c.x * invB, c.y * invB);
    d1[lane*2 + 1]  = __floats2half2_rn(c.z * invB, c.w * invB);
    d1[lane*2 + 64] = __floats2half2_rn(e.x * invB, e.y * invB);
    d1[lane*2 + 65] = __floats2half2_rn(e.z * invB, e.w * invB);
}

// ====================== 2) upper-triangular fused tile kernel ======================
// Linear grid of exactly NCTA blocks; closed-form map to (ti, tj) with ti <= tj.
__global__ __launch_bounds__(256, 2) void tile_kernel(const int* __restrict__ labels) {
    const int g = blockIdx.x;
    int ti = (int)((129.0f - sqrtf(16641.0f - 8.0f * (float)g)) * 0.5f);
    // exact fixup (sqrtf is exact at row boundaries, but be safe)
    while ((ti + 1) * (129 - (ti + 1)) / 2 <= g) ti++;
    while (ti * (129 - ti) / 2 > g) ti--;
    const int tj = ti + (g - ti * (129 - ti) / 2);

    extern __shared__ char smem[];
    const uint32_t sb = smem_u32(smem);
    const int tid = threadIdx.x;
    const int lane = tid & 31, wid = tid >> 5;
    const int wm = wid & 3, wn = wid >> 2;     // warp grid 4(m) x 2(n)
    const int i0 = ti * 128;
    const int j0 = tj * 128;

    if (tid < 128) ((int*)(smem + SM_JLAB))[tid] = labels[j0 + tid];

    // ---- prologue: A tile (128 rows x 256 halves) into 8 k-slabs of [128][32]
    #pragma unroll
    for (int q = 0; q < 16; q++) {
        const int gg = q * 256 + tid;
        const int slab = gg >> 9, w = gg & 511, r = w >> 2, c = w & 3;
        CP_ASYNC16(sb + SM_A + slab * 8192 + swz(r, c),
                   &g_xh[(size_t)(i0 + r) * D + slab * 32 + c * 8]);
    }
    CP_COMMIT();

    // B slab kk=0 -> buf0
    #pragma unroll
    for (int q = 0; q < 2; q++) {
        const int w = q * 256 + tid, r = w >> 2, c = w & 3;
        CP_ASYNC16(sb + SM_B0 + swz(r, c), &g_xh[(size_t)(j0 + r) * D + c * 8]);
    }
    CP_COMMIT();

    // per-lane ldmatrix offsets
    const int lr = (lane & 7) + ((lane >> 3) & 1) * 8;
    const int lc = lane >> 4;
    uint32_t a_off[2][2], b_off[4][2];
    #pragma unroll
    for (int mi = 0; mi < 2; mi++) {
        const int rA = wm * 32 + mi * 16 + lr;
        #pragma unroll
        for (int ks = 0; ks < 2; ks++) a_off[mi][ks] = swz(rA, 2 * ks + lc);
    }
    #pragma unroll
    for (int pr = 0; pr < 4; pr++) {
        const int rB = wn * 64 + pr * 16 + lr;
        #pragma unroll
        for (int ks = 0; ks < 2; ks++) b_off[pr][ks] = swz(rB, 2 * ks + lc);
    }

    int labm[2][2];
    #pragma unroll
    for (int mi = 0; mi < 2; mi++)
        #pragma unroll
        for (int hb = 0; hb < 2; hb++)
            labm[mi][hb] = __ldg(&labels[i0 + wm * 32 + mi * 16 + hb * 8 + (lane >> 2)]);

    float d[2][8][4];
    #pragma unroll
    for (int mi = 0; mi < 2; mi++)
        #pragma unroll
        for (int ni = 0; ni < 8; ni++)
            #pragma unroll
            for (int e = 0; e < 4; e++) d[mi][ni][e] = 0.0f;

    #pragma unroll
    for (int kk = 0; kk < 8; kk++) {
        if (kk < 7) {
            const uint32_t buf = sb + ((kk & 1) ? SM_B0 : SM_B1);
            #pragma unroll
            for (int q = 0; q < 2; q++) {
                const int w = q * 256 + tid, r = w >> 2, c = w & 3;
                CP_ASYNC16(buf + swz(r, c),
                           &g_xh[(size_t)(j0 + r) * D + (kk + 1) * 32 + c * 8]);
            }
            CP_COMMIT();
            asm volatile("cp.async.wait_group 1;" ::: "memory");
        } else {
            asm volatile("cp.async.wait_group 0;" ::: "memory");
        }
        __syncthreads();

        const uint32_t sa = sb + SM_A + kk * 8192;
        const uint32_t sbuf = sb + ((kk & 1) ? SM_B1 : SM_B0);
        #pragma unroll
        for (int ks = 0; ks < 2; ks++) {
            uint32_t a[2][4];
            ldsm_x4(a[0], sa + a_off[0][ks]);
            ldsm_x4(a[1], sa + a_off[1][ks]);
            uint32_t bf[4][4];
            #pragma unroll
            for (int pr = 0; pr < 4; pr++) ldsm_x4(bf[pr], sbuf + b_off[pr][ks]);
            #pragma unroll
            for (int mi = 0; mi < 2; mi++)
                #pragma unroll
                for (int pr = 0; pr < 4; pr++)
                    #pragma unroll
                    for (int sub = 0; sub < 2; sub++)
                        mma16816(d[mi][pr * 2 + sub], a[mi], bf[pr][sub], bf[pr][sub + 2]);
        }
        __syncthreads();
    }

    // ================= fused epilogue: row + column mining =================
    const int* jl = (const int*)(smem + SM_JLAB);
    float* scpos = (float*)(smem + SM_CPOS);
    float* scneg = (float*)(smem + SM_CNEG);

    float posmax[2][2], negmin[2][2];
    #pragma unroll
    for (int mi = 0; mi < 2; mi++)
        #pragma unroll
        for (int hb = 0; hb < 2; hb++) { posmax[mi][hb] = -1e9f; negmin[mi][hb] = 1e9f; }

    #pragma unroll
    for (int ni = 0; ni < 8; ni++) {
        const int colb = wn * 64 + ni * 8 + (lane & 3) * 2;
        const int l0 = jl[colb], l1 = jl[colb + 1];
        const int n0 = j0 + colb;
        float cp[2] = {-1e9f, -1e9f}, cn[2] = {1e9f, 1e9f};
        #pragma unroll
        for (int mi = 0; mi < 2; mi++) {
            #pragma unroll
            for (int e = 0; e < 4; e++) {
                const int hb = e >> 1, c01 = e & 1;
                const int m = i0 + wm * 32 + mi * 16 + hb * 8 + (lane >> 2);
                const int n = n0 + c01;
                const int ln = c01 ? l1 : l0;
                const float dist = fmaxf(1.0f - d[mi][ni][e], 0.0f);
                if (ln == labm[mi][hb]) {
                    if (m != n) {
                        posmax[mi][hb] = fmaxf(posmax[mi][hb], dist);
                        cp[c01] = fmaxf(cp[c01], dist);
                    }
                } else {
                    negmin[mi][hb] = fminf(negmin[mi][hb], dist);
                    cn[c01] = fminf(cn[c01], dist);
                }
            }
        }
        // reduce column partials across the 8 lanes (lane>>2) sharing these columns
        #pragma unroll
        for (int off = 4; off <= 16; off <<= 1) {
            cp[0] = fmaxf(cp[0], __shfl_xor_sync(0xffffffffu, cp[0], off));
            cp[1] = fmaxf(cp[1], __shfl_xor_sync(0xffffffffu, cp[1], off));
            cn[0] = fminf(cn[0], __shfl_xor_sync(0xffffffffu, cn[0], off));
            cn[1] = fminf(cn[1], __shfl_xor_sync(0xffffffffu, cn[1], off));
        }
        if (lane < 4) {
            const int cidx = wn * 64 + ni * 8 + lane * 2;
            scpos[wm * 128 + cidx]     = cp[0];
            scpos[wm * 128 + cidx + 1] = cp[1];
            scneg[wm * 128 + cidx]     = cn[0];
            scneg[wm * 128 + cidx + 1] = cn[1];
        }
    }

    // reduce row partials across the 4 lanes sharing each row
    #pragma unroll
    for (int mi = 0; mi < 2; mi++)
        #pragma unroll
        for (int hb = 0; hb < 2; hb++) {
            #pragma unroll
            for (int off = 1; off <= 2; off <<= 1) {
                posmax[mi][hb] = fmaxf(posmax[mi][hb], __shfl_xor_sync(0xffffffffu, posmax[mi][hb], off));
                negmin[mi][hb] = fminf(negmin[mi][hb], __shfl_xor_sync(0xffffffffu, negmin[mi][hb], off));
            }
        }
    float* srpos = (float*)(smem + SM_RPOS);
    float* srneg = (float*)(smem + SM_RNEG);
    if ((lane & 3) == 0) {
        const int gid = lane >> 2;
        #pragma unroll
        for (int mi = 0; mi < 2; mi++)
            #pragma unroll
            for (int hb = 0; hb < 2; hb++) {
                const int row = wm * 32 + mi * 16 + hb * 8 + gid;
                srpos[wn * 128 + row] = posmax[mi][hb];
                srneg[wn * 128 + row] = negmin[mi][hb];
            }
    }
    __syncthreads();
    if (tid < 128) {
        // row anchors (block ti) -> slot tj
        g_pos_part[tj * B + i0 + tid] = fmaxf(srpos[tid], srpos[128 + tid]);
        g_neg_part[tj * B + i0 + tid] = fminf(srneg[tid], srneg[128 + tid]);
        // column anchors (block tj) -> slot ti (skip on diagonal; row side covers it)
        if (ti != tj) {
            float cp = fmaxf(fmaxf(scpos[tid], scpos[128 + tid]),
                             fmaxf(scpos[256 + tid], scpos[384 + tid]));
            float cn = fminf(fminf(scneg[tid], scneg[128 + tid]),
                             fminf(scneg[256 + tid], scneg[384 + tid]));
            g_pos_part[ti * B + j0 + tid] = cp;
            g_neg_part[ti * B + j0 + tid] = cn;
        }
    }
}

// ====================== 3) combine + fused finalize ======================
// 256 blocks x 256 threads. Block handles 32 rows; warp w reduces slots
// [w*8, w*8+8) for all 32 rows with fully coalesced 128B loads.
#define CBLOCKS 256
__global__ void combine_kernel(float* __restrict__ out) {
    __shared__ float spos[8][32];
    __shared__ float sneg[8][32];
    const int tid = threadIdx.x;
    const int lane = tid & 31, w = tid >> 5;
    const int row = blockIdx.x * 32 + lane;

    float p = -1e9f, n = 1e9f;
    #pragma unroll
    for (int s8 = 0; s8 < 8; s8++) {
        const int s = w * 8 + s8;
        p = fmaxf(p, g_pos_part[s * B + row]);
        n = fminf(n, g_neg_part[s * B + row]);
    }
    spos[w][lane] = p;
    sneg[w][lane] = n;
    __syncthreads();

    if (tid < 32) {
        float pp = spos[0][lane], nn = sneg[0][lane];
        #pragma unroll
        for (int q = 1; q < 8; q++) {
            pp = fmaxf(pp, spos[q][lane]);
            nn = fminf(nn, sneg[q][lane]);
        }
        const bool valid = (pp > -1e8f) && (nn < 1e8f);
        float per = valid ? fmaxf(pp - nn + 1.0f, 0.0f) : 0.0f;  // MARGIN = 1.0
        int cnt = valid ? 1 : 0;
        #pragma unroll
        for (int o = 16; o > 0; o >>= 1) {
            per += __shfl_xor_sync(0xffffffffu, per, o);
            cnt += __shfl_xor_sync(0xffffffffu, cnt, o);
        }
        if (lane == 0) {
            atomicAdd(&g_sum, per);
            atomicAdd(&g_cnt, cnt);
            __threadfence();
            const unsigned int rank = atomicAdd(&g_done, 1u);
            if (rank == CBLOCKS - 1) {
                const float total = atomicAdd(&g_sum, 0.0f);
                const int c = atomicAdd(&g_cnt, 0);
                const float cf = (float)c;
                out[0] = (cf > 0.0f) ? (total / fmaxf(cf, 1.0f)) : 0.0f;
            }
        }
    }
}

// ======================================================================
extern "C" void kernel_launch(void* const* d_in, const int* in_sizes, int n_in,
                              void* d_out, int out_size) {
    const float* emb = (const float*)d_in[0];
    const int* labels = (const int*)d_in[1];
    float* out = (float*)d_out;

    cudaFuncSetAttribute(tile_kernel, cudaFuncAttributeMaxDynamicSharedMemorySize, SMEM_TOTAL);

    normalize_kernel<<<B / 2 / 8, 256>>>(emb);       // 512 blocks, 2 rows/warp
    tile_kernel<<<NCTA, 256, SMEM_TOTAL>>>(labels);
    combine_kernel<<<CBLOCKS, 256>>>(out);
}